// round 1
// baseline (speedup 1.0000x reference)
#include <cuda_runtime.h>
#include <math.h>

#define T_STEPS 512
#define BATCH   256
#define OBSD    256
#define HIDD    512
#define LSTMD   512
#define ACTD    32
#define ROWS    (T_STEPS * BATCH)   /* 131072 */

// ---------------- scratch (static device globals; no runtime allocation) ----
__device__ float g_feats[(size_t)ROWS * HIDD];          // 256 MB
__device__ float g_gates[(size_t)ROWS * 4 * LSTMD];     // 1 GB
__device__ float g_ys   [(size_t)ROWS * LSTMD];         // 256 MB
__device__ float g_h0   [BATCH * LSTMD];                // zero h for t=0
__device__ float g_c    [BATCH * LSTMD];                // cell state

__device__ __forceinline__ float gelu_f(float x) {
    float x3 = x * x * x;
    float t  = tanhf(0.7978845608028654f * (x + 0.044715f * x3));
    return 0.5f * x * (1.0f + t);
}
__device__ __forceinline__ float sigm(float x) { return 1.0f / (1.0f + expf(-x)); }

// ---------------- zero fill -------------------------------------------------
__global__ void zero_kernel(float* p, int n) {
    int i = blockIdx.x * blockDim.x + threadIdx.x;
    if (i < n) p[i] = 0.0f;
}

// ---------------- generic fp32 GEMM: C = act(A[M,K] * B[K,N] + bias[N]) -----
// BM=128, BN=64, BK=16, 256 threads, 8x4 per-thread microtile.
// Requires M%128==0, N%64==0, K%16==0, pointers 16B aligned (true here).
__global__ void gemm_bias_act(const float* __restrict__ A,
                              const float* __restrict__ B,
                              const float* __restrict__ bias,
                              float* __restrict__ C,
                              int M, int N, int K, int do_gelu)
{
    __shared__ float As[16][128];
    __shared__ float Bs[16][64];

    const int bm = blockIdx.y * 128;
    const int bn = blockIdx.x * 64;
    const int tid = threadIdx.x;
    const int tx = tid & 15;    // n-direction (x4)
    const int ty = tid >> 4;    // m-direction (x8)

    float acc[8][4];
#pragma unroll
    for (int i = 0; i < 8; i++)
#pragma unroll
        for (int j = 0; j < 4; j++) acc[i][j] = 0.0f;

    const int a_row = tid >> 2;          // 0..63 (plus +64)
    const int a_col = (tid & 3) << 2;    // 0,4,8,12
    const int b_row = tid >> 4;          // 0..15
    const int b_col = (tid & 15) << 2;   // 0..60

    for (int k0 = 0; k0 < K; k0 += 16) {
#pragma unroll
        for (int i = 0; i < 2; i++) {
            int r = a_row + i * 64;
            float4 v = *reinterpret_cast<const float4*>(
                A + (size_t)(bm + r) * K + k0 + a_col);
            As[a_col + 0][r] = v.x;
            As[a_col + 1][r] = v.y;
            As[a_col + 2][r] = v.z;
            As[a_col + 3][r] = v.w;
        }
        {
            float4 w = *reinterpret_cast<const float4*>(
                B + (size_t)(k0 + b_row) * N + bn + b_col);
            *reinterpret_cast<float4*>(&Bs[b_row][b_col]) = w;
        }
        __syncthreads();

#pragma unroll
        for (int kk = 0; kk < 16; kk++) {
            float ar[8], br[4];
#pragma unroll
            for (int i = 0; i < 8; i++) ar[i] = As[kk][ty * 8 + i];
#pragma unroll
            for (int j = 0; j < 4; j++) br[j] = Bs[kk][tx * 4 + j];
#pragma unroll
            for (int i = 0; i < 8; i++)
#pragma unroll
                for (int j = 0; j < 4; j++)
                    acc[i][j] = fmaf(ar[i], br[j], acc[i][j]);
        }
        __syncthreads();
    }

#pragma unroll
    for (int i = 0; i < 8; i++) {
        float4 o;
        float* po = &o.x;
#pragma unroll
        for (int j = 0; j < 4; j++) {
            float v = acc[i][j] + bias[bn + tx * 4 + j];
            if (do_gelu) v = gelu_f(v);
            po[j] = v;
        }
        *reinterpret_cast<float4*>(C + (size_t)(bm + ty * 8 + i) * N + bn + tx * 4) = o;
    }
}

// ---------------- fused LSTM step ------------------------------------------
// z[b, g, j] = gates_x[t][b][g*512+j] + sum_k h_in[b][k] * W_h[k][g*512+j]
// then cell/gate update; writes h to h_out (= ys[t]) and updates g_c.
// Tile: 32 b x 32 j, 256 threads (tx = j lane, ty = 0..7, 4 b per thread),
// each thread holds all four gates for its (b,j) so elementwise fuses in-place.
__global__ void lstm_step_kernel(const float* __restrict__ Wh,
                                 const float* __restrict__ h_in,
                                 float* __restrict__ h_out,
                                 int t)
{
    __shared__ float Hs[32][33];    // [k][b], padded
    __shared__ float Ws[32][128];   // [k][g*32+j]

    const int j0 = blockIdx.x * 32;
    const int b0 = blockIdx.y * 32;
    const int tid = threadIdx.x;
    const int tx = tid & 31;        // j
    const int ty = tid >> 5;        // 0..7

    const float* gates_t = g_gates + (size_t)t * BATCH * 4 * LSTMD;

    float acc[4][4];  // [gate][b_sub]
#pragma unroll
    for (int g = 0; g < 4; g++)
#pragma unroll
        for (int i = 0; i < 4; i++)
            acc[g][i] = gates_t[(size_t)(b0 + ty * 4 + i) * (4 * LSTMD)
                                + g * LSTMD + j0 + tx];

    const int lb = tid >> 3;          // 0..31 (b row to load)
    const int lk = (tid & 7) << 2;    // k quad

    for (int k0 = 0; k0 < LSTMD; k0 += 32) {
        float4 hv = *reinterpret_cast<const float4*>(
            h_in + (size_t)(b0 + lb) * LSTMD + k0 + lk);
        Hs[lk + 0][lb] = hv.x;
        Hs[lk + 1][lb] = hv.y;
        Hs[lk + 2][lb] = hv.z;
        Hs[lk + 3][lb] = hv.w;

#pragma unroll
        for (int it = 0; it < 4; it++) {
            int f   = tid + 256 * it;     // 0..1023 float4 slots
            int kr  = f >> 5;             // 0..31
            int cit = (f & 31) << 2;      // 0..124 (col in 128-wide tile)
            int g   = cit >> 5;           // gate
            int jj  = cit & 31;
            float4 wv = *reinterpret_cast<const float4*>(
                Wh + (size_t)(k0 + kr) * (4 * LSTMD) + g * LSTMD + j0 + jj);
            *reinterpret_cast<float4*>(&Ws[kr][cit]) = wv;
        }
        __syncthreads();

#pragma unroll
        for (int kk = 0; kk < 32; kk++) {
            float hr[4], wr[4];
#pragma unroll
            for (int i = 0; i < 4; i++) hr[i] = Hs[kk][ty * 4 + i];
#pragma unroll
            for (int g = 0; g < 4; g++) wr[g] = Ws[kk][g * 32 + tx];
#pragma unroll
            for (int g = 0; g < 4; g++)
#pragma unroll
                for (int i = 0; i < 4; i++)
                    acc[g][i] = fmaf(hr[i], wr[g], acc[g][i]);
        }
        __syncthreads();
    }

#pragma unroll
    for (int i = 0; i < 4; i++) {
        int b = b0 + ty * 4 + i;
        size_t idx = (size_t)b * LSTMD + j0 + tx;
        float c_old = g_c[idx];
        float ig = sigm(acc[0][i]);
        float fg = sigm(acc[1][i]);
        float gg = tanhf(acc[2][i]);
        float og = sigm(acc[3][i]);
        float c_new = fg * c_old + ig * gg;
        float h = og * tanhf(c_new);
        g_c[idx]   = c_new;
        h_out[idx] = h;
    }
}

// ---------------- heads: mu / sigma / value, one pass over ys ---------------
// blockDim (32, 8): warp per (t,b) row; lane = action index.
__global__ void heads_kernel(const float* __restrict__ Wmu,
                             const float* __restrict__ bmu,
                             const float* __restrict__ logstd,
                             const float* __restrict__ Wv,
                             const float* __restrict__ bv,
                             float* __restrict__ out)
{
    const int lane = threadIdx.x;
    const size_t row = (size_t)blockIdx.x * blockDim.y + threadIdx.y;
    const float* yrow = g_ys + row * LSTMD;

    float acc = 0.0f;
#pragma unroll 8
    for (int k = 0; k < LSTMD; k++)
        acc = fmaf(yrow[k], Wmu[k * ACTD + lane], acc);

    float* mu    = out;
    float* sigma = out + (size_t)ROWS * ACTD;
    float* value = out + (size_t)2 * ROWS * ACTD;

    mu[row * ACTD + lane]    = acc + bmu[lane];
    sigma[row * ACTD + lane] = expf(logstd[lane]);

    float v = 0.0f;
    for (int k = lane; k < LSTMD; k += 32)
        v = fmaf(yrow[k], Wv[k], v);
#pragma unroll
    for (int o = 16; o; o >>= 1) v += __shfl_xor_sync(0xffffffffu, v, o);
    if (lane == 0) value[row] = v + bv[0];
}

// ---------------- launch ----------------------------------------------------
extern "C" void kernel_launch(void* const* d_in, const int* in_sizes, int n_in,
                              void* d_out, int out_size)
{
    (void)in_sizes; (void)n_in; (void)out_size;
    const float* x      = (const float*)d_in[0];
    const float* W_enc  = (const float*)d_in[1];
    const float* b_enc  = (const float*)d_in[2];
    const float* W_i    = (const float*)d_in[3];
    const float* W_h    = (const float*)d_in[4];
    const float* b_lstm = (const float*)d_in[5];
    const float* W_mu   = (const float*)d_in[6];
    const float* b_mu   = (const float*)d_in[7];
    const float* logstd = (const float*)d_in[8];
    const float* W_v    = (const float*)d_in[9];
    const float* b_v    = (const float*)d_in[10];
    float* out = (float*)d_out;

    float *feats, *ys, *h0, *c;
    cudaGetSymbolAddress((void**)&feats, g_feats);
    cudaGetSymbolAddress((void**)&ys,    g_ys);
    cudaGetSymbolAddress((void**)&h0,    g_h0);
    cudaGetSymbolAddress((void**)&c,     g_c);
    float* gates;
    cudaGetSymbolAddress((void**)&gates, g_gates);

    // zero h0 / c each call (deterministic)
    {
        int n = BATCH * LSTMD;
        zero_kernel<<<(n + 255) / 256, 256>>>(h0, n);
        zero_kernel<<<(n + 255) / 256, 256>>>(c,  n);
    }

    // encoder: feats = gelu(x @ W_enc + b_enc)   [131072 x 512, K=256]
    {
        dim3 grid(HIDD / 64, ROWS / 128);
        gemm_bias_act<<<grid, 256>>>(x, W_enc, b_enc, feats, ROWS, HIDD, OBSD, 1);
    }
    // gates_x = feats @ W_i + b_lstm             [131072 x 2048, K=512]
    {
        dim3 grid((4 * LSTMD) / 64, ROWS / 128);
        gemm_bias_act<<<grid, 256>>>(feats, W_i, b_lstm, gates, ROWS, 4 * LSTMD, HIDD, 0);
    }
    // recurrence: 512 fused step kernels; h flows through ys itself
    {
        dim3 grid(LSTMD / 32, BATCH / 32);   // (16, 8) = 128 blocks
        for (int t = 0; t < T_STEPS; t++) {
            const float* hin = (t == 0) ? h0 : ys + (size_t)(t - 1) * BATCH * LSTMD;
            float* hout = ys + (size_t)t * BATCH * LSTMD;
            lstm_step_kernel<<<grid, 256>>>(W_h, hin, hout, t);
        }
    }
    // heads
    {
        dim3 blk(32, 8);
        heads_kernel<<<ROWS / 8, blk>>>(W_mu, b_mu, logstd, W_v, b_v, out);
    }
}

// round 2
// speedup vs baseline: 1.0754x; 1.0754x over previous
#include <cuda_runtime.h>
#include <math.h>

#define T_STEPS 512
#define BATCH   256
#define OBSD    256
#define HIDD    512
#define LSTMD   512
#define ACTD    32
#define ROWS    (T_STEPS * BATCH)   /* 131072 */
#define GATES_N (4 * LSTMD)         /* 2048 */

// ---------------- scratch (static device globals; no runtime allocation) ----
__device__ float    g_feats[(size_t)ROWS * HIDD];          // 256 MB
__device__ float    g_gates[(size_t)ROWS * GATES_N];       // 1 GB (permuted 4j+g layout)
__device__ float    g_ys   [(size_t)ROWS * LSTMD];         // 256 MB
__device__ float    g_h0   [BATCH * LSTMD];
__device__ float    g_c    [BATCH * LSTMD];
__device__ float    g_WiP  [(size_t)HIDD * GATES_N];       // permuted W_i (fp32)
__device__ unsigned g_WhP  [(size_t)LSTMD * GATES_N];      // permuted W_h (tf32 bits)
__device__ float    g_bP   [GATES_N];                      // permuted b_lstm

__device__ __forceinline__ float gelu_f(float x) {
    float x3 = x * x * x;
    float t  = tanhf(0.7978845608028654f * (x + 0.044715f * x3));
    return 0.5f * x * (1.0f + t);
}
__device__ __forceinline__ float sigm(float x) { return 1.0f / (1.0f + expf(-x)); }

__device__ __forceinline__ unsigned f2tf32(float x) {
    unsigned u;
    asm("cvt.rna.tf32.f32 %0, %1;" : "=r"(u) : "f"(x));
    return u;
}

__device__ __forceinline__ void mma_tf32(float c[4],
                                         unsigned a0, unsigned a1, unsigned a2, unsigned a3,
                                         unsigned b0, unsigned b1) {
    asm volatile(
        "mma.sync.aligned.m16n8k8.row.col.f32.tf32.tf32.f32 "
        "{%0,%1,%2,%3}, {%4,%5,%6,%7}, {%8,%9}, {%0,%1,%2,%3};\n"
        : "+f"(c[0]), "+f"(c[1]), "+f"(c[2]), "+f"(c[3])
        : "r"(a0), "r"(a1), "r"(a2), "r"(a3), "r"(b0), "r"(b1));
}

// ---------------- small utility kernels -------------------------------------
__global__ void zero_kernel(float* p, int n) {
    int i = blockIdx.x * blockDim.x + threadIdx.x;
    if (i < n) p[i] = 0.0f;
}

// Wp[k][4j+g] = W[k][g*512+j]  (fp32 copy)
__global__ void permute_wi(const float* __restrict__ W, float* __restrict__ Wp) {
    int idx = blockIdx.x * 256 + threadIdx.x;       // < 512*2048
    int k = idx >> 11, c = idx & 2047;
    Wp[idx] = W[(size_t)k * GATES_N + (c & 3) * LSTMD + (c >> 2)];
}
// Wp[k][4j+g] = tf32(W[k][g*512+j])
__global__ void permute_wh(const float* __restrict__ W, unsigned* __restrict__ Wp) {
    int idx = blockIdx.x * 256 + threadIdx.x;
    int k = idx >> 11, c = idx & 2047;
    Wp[idx] = f2tf32(W[(size_t)k * GATES_N + (c & 3) * LSTMD + (c >> 2)]);
}
__global__ void permute_b(const float* __restrict__ b, float* __restrict__ bp) {
    int idx = blockIdx.x * 256 + threadIdx.x;
    if (idx < GATES_N) bp[idx] = b[(idx & 3) * LSTMD + (idx >> 2)];
}

// ---------------- big GEMM: C = act(A[M,K] @ B[K,N] + bias) via TF32 mma ----
// BM=128, BN=128, BK=32, 256 threads (8 warps: 2m x 4n of 64x32 warp tiles).
__global__ void gemm_mma(const float* __restrict__ A,
                         const float* __restrict__ B,
                         const float* __restrict__ bias,
                         float* __restrict__ C,
                         int M, int N, int K, int do_gelu)
{
    __shared__ unsigned As[128][36];   // [m][k], stride 36 -> conflict-free frags
    __shared__ unsigned Bs[32][136];   // [k][n], stride 136 -> conflict-free frags

    const int bm = blockIdx.y * 128;
    const int bn = blockIdx.x * 128;
    const int tid  = threadIdx.x;
    const int warp = tid >> 5;
    const int lane = tid & 31;
    const int wm = (warp & 1) * 64;
    const int wn = (warp >> 1) * 32;
    const int r  = lane >> 2;
    const int q  = lane & 3;

    float acc[4][4][4];
#pragma unroll
    for (int mt = 0; mt < 4; mt++)
#pragma unroll
        for (int nt = 0; nt < 4; nt++)
#pragma unroll
            for (int i = 0; i < 4; i++) acc[mt][nt][i] = 0.0f;

    const float* Ab = A + (size_t)bm * K;

    for (int k0 = 0; k0 < K; k0 += 32) {
#pragma unroll
        for (int it = 0; it < 4; it++) {          // A: 128x32
            int i  = tid + it * 256;
            int m  = i >> 3;
            int kq = (i & 7) * 4;
            float4 v = *reinterpret_cast<const float4*>(Ab + (size_t)m * K + k0 + kq);
            unsigned* d = &As[m][kq];
            d[0] = f2tf32(v.x); d[1] = f2tf32(v.y);
            d[2] = f2tf32(v.z); d[3] = f2tf32(v.w);
        }
#pragma unroll
        for (int it = 0; it < 4; it++) {          // B: 32x128
            int i  = tid + it * 256;
            int kr = i >> 5;
            int nq = (i & 31) * 4;
            float4 v = *reinterpret_cast<const float4*>(B + (size_t)(k0 + kr) * N + bn + nq);
            unsigned* d = &Bs[kr][nq];
            d[0] = f2tf32(v.x); d[1] = f2tf32(v.y);
            d[2] = f2tf32(v.z); d[3] = f2tf32(v.w);
        }
        __syncthreads();

#pragma unroll
        for (int kk = 0; kk < 32; kk += 8) {
            unsigned af[4][4], bf[4][2];
#pragma unroll
            for (int mt = 0; mt < 4; mt++) {
                int mb = wm + mt * 16;
                af[mt][0] = As[mb + r    ][kk + q];
                af[mt][1] = As[mb + r + 8][kk + q];
                af[mt][2] = As[mb + r    ][kk + q + 4];
                af[mt][3] = As[mb + r + 8][kk + q + 4];
            }
#pragma unroll
            for (int nt = 0; nt < 4; nt++) {
                int nb = wn + nt * 8 + r;
                bf[nt][0] = Bs[kk + q    ][nb];
                bf[nt][1] = Bs[kk + q + 4][nb];
            }
#pragma unroll
            for (int mt = 0; mt < 4; mt++)
#pragma unroll
                for (int nt = 0; nt < 4; nt++)
                    mma_tf32(acc[mt][nt], af[mt][0], af[mt][1], af[mt][2], af[mt][3],
                             bf[nt][0], bf[nt][1]);
        }
        __syncthreads();
    }

#pragma unroll
    for (int mt = 0; mt < 4; mt++) {
#pragma unroll
        for (int nt = 0; nt < 4; nt++) {
            int row = bm + wm + mt * 16 + r;
            int col = bn + wn + nt * 8 + 2 * q;
            float b0 = bias[col], b1 = bias[col + 1];
            float z00 = acc[mt][nt][0] + b0, z01 = acc[mt][nt][1] + b1;
            float z10 = acc[mt][nt][2] + b0, z11 = acc[mt][nt][3] + b1;
            if (do_gelu) {
                z00 = gelu_f(z00); z01 = gelu_f(z01);
                z10 = gelu_f(z10); z11 = gelu_f(z11);
            }
            float2 o0 = make_float2(z00, z01);
            float2 o1 = make_float2(z10, z11);
            *reinterpret_cast<float2*>(C + (size_t)row * N + col) = o0;
            *reinterpret_cast<float2*>(C + (size_t)(row + 8) * N + col) = o1;
        }
    }
}

// ---------------- fused TF32-mma LSTM step ----------------------------------
// z[b][4j+g] = gx[b][4j+g] + sum_k h_in[b][k] * WhP[k][4j+g]; then gate fuse.
// BM=128 (batch), BN=64, BK=32; 8 warps (4m x 2n of 32x32 warp tiles).
__global__ void lstm_step_mma(const unsigned* __restrict__ Wp,
                              const float* __restrict__ h_in,
                              float* __restrict__ h_out,
                              const float* __restrict__ gates_t)
{
    __shared__ unsigned As[128][36];   // h tile [m][k]
    __shared__ unsigned Bs[32][72];    // W tile [k][n]

    const int bm = blockIdx.y * 128;
    const int bn = blockIdx.x * 64;
    const int tid  = threadIdx.x;
    const int warp = tid >> 5;
    const int lane = tid & 31;
    const int wm = (warp & 3) * 32;
    const int wn = (warp >> 2) * 32;
    const int r  = lane >> 2;
    const int q  = lane & 3;
    const int p  = q & 1;     // 0: holds (i,f) cols; 1: holds (g,o) cols

    float acc[2][4][4];
#pragma unroll
    for (int mt = 0; mt < 2; mt++)
#pragma unroll
        for (int nt = 0; nt < 4; nt++)
#pragma unroll
            for (int i = 0; i < 4; i++) acc[mt][nt][i] = 0.0f;

    for (int k0 = 0; k0 < LSTMD; k0 += 32) {
#pragma unroll
        for (int it = 0; it < 4; it++) {          // h: 128x32, cvt to tf32
            int i  = tid + it * 256;
            int m  = i >> 3;
            int kq = (i & 7) * 4;
            float4 v = *reinterpret_cast<const float4*>(
                h_in + (size_t)(bm + m) * LSTMD + k0 + kq);
            unsigned* d = &As[m][kq];
            d[0] = f2tf32(v.x); d[1] = f2tf32(v.y);
            d[2] = f2tf32(v.z); d[3] = f2tf32(v.w);
        }
#pragma unroll
        for (int it = 0; it < 2; it++) {          // W: 32x64, already tf32
            int i  = tid + it * 256;
            int kr = i >> 4;
            int nq = (i & 15) * 4;
            uint4 v = *reinterpret_cast<const uint4*>(
                Wp + (size_t)(k0 + kr) * GATES_N + bn + nq);
            *reinterpret_cast<uint4*>(&Bs[kr][nq]) = v;
        }
        __syncthreads();

#pragma unroll
        for (int kk = 0; kk < 32; kk += 8) {
            unsigned af[2][4], bf[4][2];
#pragma unroll
            for (int mt = 0; mt < 2; mt++) {
                int mb = wm + mt * 16;
                af[mt][0] = As[mb + r    ][kk + q];
                af[mt][1] = As[mb + r + 8][kk + q];
                af[mt][2] = As[mb + r    ][kk + q + 4];
                af[mt][3] = As[mb + r + 8][kk + q + 4];
            }
#pragma unroll
            for (int nt = 0; nt < 4; nt++) {
                int nb = wn + nt * 8 + r;
                bf[nt][0] = Bs[kk + q    ][nb];
                bf[nt][1] = Bs[kk + q + 4][nb];
            }
#pragma unroll
            for (int mt = 0; mt < 2; mt++)
#pragma unroll
                for (int nt = 0; nt < 4; nt++)
                    mma_tf32(acc[mt][nt], af[mt][0], af[mt][1], af[mt][2], af[mt][3],
                             bf[nt][0], bf[nt][1]);
        }
        __syncthreads();
    }

    // epilogue: add gx, gate math via lane-pair shuffle (cols 4j+{0,1,2,3})
#pragma unroll
    for (int mt = 0; mt < 2; mt++) {
#pragma unroll
        for (int nt = 0; nt < 4; nt++) {
            int row = bm + wm + mt * 16 + r;
            int col = bn + wn + nt * 8 + 2 * q;   // even
            float2 gx0 = *reinterpret_cast<const float2*>(
                gates_t + (size_t)row * GATES_N + col);
            float2 gx1 = *reinterpret_cast<const float2*>(
                gates_t + (size_t)(row + 8) * GATES_N + col);
            float z00 = acc[mt][nt][0] + gx0.x, z01 = acc[mt][nt][1] + gx0.y;
            float z10 = acc[mt][nt][2] + gx1.x, z11 = acc[mt][nt][3] + gx1.y;

            // p==0: (z00,z01)=(i,f) -> (sigm,sigm); p==1: (g,o) -> (tanh,sigm)
            float u0a = (p == 0) ? sigm(z00) : tanhf(z00);
            float u1a = sigm(z01);
            float u0b = (p == 0) ? sigm(z10) : tanhf(z10);
            float u1b = sigm(z11);

            float v0a = __shfl_xor_sync(0xffffffffu, u0a, 1);
            float v1a = __shfl_xor_sync(0xffffffffu, u1a, 1);
            float v0b = __shfl_xor_sync(0xffffffffu, u0b, 1);
            float v1b = __shfl_xor_sync(0xffffffffu, u1b, 1);

            if (p == 0) {
                int j = col >> 2;
                size_t ia = (size_t)row * LSTMD + j;
                float co = g_c[ia];
                float cn = u1a * co + u0a * v0a;      // sigm(f)*c + sigm(i)*tanh(g)
                g_c[ia] = cn;
                h_out[ia] = v1a * tanhf(cn);          // sigm(o)*tanh(c)
                size_t ib = (size_t)(row + 8) * LSTMD + j;
                float cb = g_c[ib];
                float cnb = u1b * cb + u0b * v0b;
                g_c[ib] = cnb;
                h_out[ib] = v1b * tanhf(cnb);
            }
        }
    }
}

// ---------------- heads: mu / sigma / value, one pass over ys ---------------
__global__ void heads_kernel(const float* __restrict__ Wmu,
                             const float* __restrict__ bmu,
                             const float* __restrict__ logstd,
                             const float* __restrict__ Wv,
                             const float* __restrict__ bv,
                             float* __restrict__ out)
{
    const int lane = threadIdx.x;
    const size_t row = (size_t)blockIdx.x * blockDim.y + threadIdx.y;
    const float* yrow = g_ys + row * LSTMD;

    float acc = 0.0f;
#pragma unroll 8
    for (int k = 0; k < LSTMD; k++)
        acc = fmaf(yrow[k], Wmu[k * ACTD + lane], acc);

    float* mu    = out;
    float* sigma = out + (size_t)ROWS * ACTD;
    float* value = out + (size_t)2 * ROWS * ACTD;

    mu[row * ACTD + lane]    = acc + bmu[lane];
    sigma[row * ACTD + lane] = expf(logstd[lane]);

    float v = 0.0f;
    for (int k = lane; k < LSTMD; k += 32)
        v = fmaf(yrow[k], Wv[k], v);
#pragma unroll
    for (int o = 16; o; o >>= 1) v += __shfl_xor_sync(0xffffffffu, v, o);
    if (lane == 0) value[row] = v + bv[0];
}

// ---------------- launch ----------------------------------------------------
extern "C" void kernel_launch(void* const* d_in, const int* in_sizes, int n_in,
                              void* d_out, int out_size)
{
    (void)in_sizes; (void)n_in; (void)out_size;
    const float* x      = (const float*)d_in[0];
    const float* W_enc  = (const float*)d_in[1];
    const float* b_enc  = (const float*)d_in[2];
    const float* W_i    = (const float*)d_in[3];
    const float* W_h    = (const float*)d_in[4];
    const float* b_lstm = (const float*)d_in[5];
    const float* W_mu   = (const float*)d_in[6];
    const float* b_mu   = (const float*)d_in[7];
    const float* logstd = (const float*)d_in[8];
    const float* W_v    = (const float*)d_in[9];
    const float* b_v    = (const float*)d_in[10];
    float* out = (float*)d_out;

    float *feats, *gates, *ys, *h0, *c, *WiP, *bP;
    unsigned* WhP;
    cudaGetSymbolAddress((void**)&feats, g_feats);
    cudaGetSymbolAddress((void**)&gates, g_gates);
    cudaGetSymbolAddress((void**)&ys,    g_ys);
    cudaGetSymbolAddress((void**)&h0,    g_h0);
    cudaGetSymbolAddress((void**)&c,     g_c);
    cudaGetSymbolAddress((void**)&WiP,   g_WiP);
    cudaGetSymbolAddress((void**)&WhP,   g_WhP);
    cudaGetSymbolAddress((void**)&bP,    g_bP);

    // zero h0 / c
    {
        int n = BATCH * LSTMD;
        zero_kernel<<<(n + 255) / 256, 256>>>(h0, n);
        zero_kernel<<<(n + 255) / 256, 256>>>(c,  n);
    }
    // permute weights into 4j+g interleaved layout (W_h also -> tf32)
    permute_wi<<<(HIDD * GATES_N) / 256, 256>>>(W_i, WiP);
    permute_wh<<<(LSTMD * GATES_N) / 256, 256>>>(W_h, WhP);
    permute_b<<<(GATES_N + 255) / 256, 256>>>(b_lstm, bP);

    // encoder: feats = gelu(x @ W_enc + b_enc)   [131072 x 512, K=256]
    {
        dim3 grid(HIDD / 128, ROWS / 128);
        gemm_mma<<<grid, 256>>>(x, W_enc, b_enc, feats, ROWS, HIDD, OBSD, 1);
    }
    // gates = feats @ WiP + bP   (permuted cols)  [131072 x 2048, K=512]
    {
        dim3 grid(GATES_N / 128, ROWS / 128);
        gemm_mma<<<grid, 256>>>(feats, WiP, bP, gates, ROWS, GATES_N, HIDD, 0);
    }
    // recurrence: 512 fused tf32-mma steps
    {
        dim3 grid(GATES_N / 64, BATCH / 128);   // (32, 2) = 64 blocks
        for (int t = 0; t < T_STEPS; t++) {
            const float* hin = (t == 0) ? h0 : ys + (size_t)(t - 1) * BATCH * LSTMD;
            float* hout = ys + (size_t)t * BATCH * LSTMD;
            const float* gx = gates + (size_t)t * BATCH * GATES_N;
            lstm_step_mma<<<grid, 256>>>(WhP, hin, hout, gx);
        }
    }
    // heads
    {
        dim3 blk(32, 8);
        heads_kernel<<<ROWS / 8, blk>>>(W_mu, b_mu, logstd, W_v, b_v, out);
    }
}

// round 3
// speedup vs baseline: 2.0486x; 1.9050x over previous
#include <cuda_runtime.h>
#include <math.h>

#define T_STEPS 512
#define BATCH   256
#define OBSD    256
#define HIDD    512
#define LSTMD   512
#define ACTD    32
#define ROWS    (T_STEPS * BATCH)   /* 131072 */
#define GATES_N (4 * LSTMD)         /* 2048 */
#define HT_ELEMS (BATCH * LSTMD)    /* 131072 */

// ---------------- scratch (static device globals; no runtime allocation) ----
__device__ float    g_feats[(size_t)ROWS * HIDD];          // 256 MB
__device__ float    g_gates[(size_t)ROWS * GATES_N];       // 1 GB (permuted 4j+g layout)
__device__ float    g_ys   [(size_t)ROWS * LSTMD];         // 256 MB
__device__ float    g_hT   [2 * HT_ELEMS];                 // ping-pong h (tf32-rounded)
__device__ float    g_WiP  [(size_t)HIDD * GATES_N];       // permuted W_i (fp32)
__device__ unsigned g_WhP  [(size_t)LSTMD * GATES_N];      // permuted W_h (tf32 bits)
__device__ float    g_bP   [GATES_N];                      // permuted b_lstm
__device__ unsigned g_bar;                                 // grid barrier counter

__device__ __forceinline__ float gelu_f(float x) {
    float x3 = x * x * x;
    float t  = tanhf(0.7978845608028654f * (x + 0.044715f * x3));
    return 0.5f * x * (1.0f + t);
}
__device__ __forceinline__ float sigm(float x) { return 1.0f / (1.0f + expf(-x)); }

__device__ __forceinline__ unsigned f2tf32(float x) {
    unsigned u;
    asm("cvt.rna.tf32.f32 %0, %1;" : "=r"(u) : "f"(x));
    return u;
}

__device__ __forceinline__ void mma_tf32(float c[4],
                                         unsigned a0, unsigned a1, unsigned a2, unsigned a3,
                                         unsigned b0, unsigned b1) {
    asm volatile(
        "mma.sync.aligned.m16n8k8.row.col.f32.tf32.tf32.f32 "
        "{%0,%1,%2,%3}, {%4,%5,%6,%7}, {%8,%9}, {%0,%1,%2,%3};\n"
        : "+f"(c[0]), "+f"(c[1]), "+f"(c[2]), "+f"(c[3])
        : "r"(a0), "r"(a1), "r"(a2), "r"(a3), "r"(b0), "r"(b1));
}

__device__ __forceinline__ void cp16(void* smem_dst, const void* gsrc) {
    unsigned d = (unsigned)__cvta_generic_to_shared(smem_dst);
    asm volatile("cp.async.ca.shared.global [%0], [%1], 16;\n" :: "r"(d), "l"(gsrc));
}
__device__ __forceinline__ void cp_commit() {
    asm volatile("cp.async.commit_group;\n");
}
template <int N>
__device__ __forceinline__ void cp_wait() {
    asm volatile("cp.async.wait_group %0;\n" :: "n"(N));
}

// ---------------- small utility kernels -------------------------------------
__global__ void zero_kernel(float* p, int n) {
    int i = blockIdx.x * blockDim.x + threadIdx.x;
    if (i < n) p[i] = 0.0f;
}
__global__ void zero_bar() { g_bar = 0u; }

// Wp[k][4j+g] = W[k][g*512+j]  (fp32 copy)
__global__ void permute_wi(const float* __restrict__ W, float* __restrict__ Wp) {
    int idx = blockIdx.x * 256 + threadIdx.x;       // < 512*2048
    int k = idx >> 11, c = idx & 2047;
    Wp[idx] = W[(size_t)k * GATES_N + (c & 3) * LSTMD + (c >> 2)];
}
// Wp[k][4j+g] = tf32(W[k][g*512+j])
__global__ void permute_wh(const float* __restrict__ W, unsigned* __restrict__ Wp) {
    int idx = blockIdx.x * 256 + threadIdx.x;
    int k = idx >> 11, c = idx & 2047;
    Wp[idx] = f2tf32(W[(size_t)k * GATES_N + (c & 3) * LSTMD + (c >> 2)]);
}
__global__ void permute_b(const float* __restrict__ b, float* __restrict__ bp) {
    int idx = blockIdx.x * 256 + threadIdx.x;
    if (idx < GATES_N) bp[idx] = b[(idx & 3) * LSTMD + (idx >> 2)];
}

// ---------------- big GEMM: C = act(A[M,K] @ B[K,N] + bias) via TF32 mma ----
// BM=128, BN=128, BK=32, 256 threads (8 warps: 2m x 4n of 64x32 warp tiles).
__global__ void gemm_mma(const float* __restrict__ A,
                         const float* __restrict__ B,
                         const float* __restrict__ bias,
                         float* __restrict__ C,
                         int M, int N, int K, int do_gelu)
{
    __shared__ unsigned As[128][36];
    __shared__ unsigned Bs[32][136];

    const int bm = blockIdx.y * 128;
    const int bn = blockIdx.x * 128;
    const int tid  = threadIdx.x;
    const int warp = tid >> 5;
    const int lane = tid & 31;
    const int wm = (warp & 1) * 64;
    const int wn = (warp >> 1) * 32;
    const int r  = lane >> 2;
    const int q  = lane & 3;

    float acc[4][4][4];
#pragma unroll
    for (int mt = 0; mt < 4; mt++)
#pragma unroll
        for (int nt = 0; nt < 4; nt++)
#pragma unroll
            for (int i = 0; i < 4; i++) acc[mt][nt][i] = 0.0f;

    const float* Ab = A + (size_t)bm * K;

    for (int k0 = 0; k0 < K; k0 += 32) {
#pragma unroll
        for (int it = 0; it < 4; it++) {          // A: 128x32
            int i  = tid + it * 256;
            int m  = i >> 3;
            int kq = (i & 7) * 4;
            float4 v = *reinterpret_cast<const float4*>(Ab + (size_t)m * K + k0 + kq);
            unsigned* d = &As[m][kq];
            d[0] = f2tf32(v.x); d[1] = f2tf32(v.y);
            d[2] = f2tf32(v.z); d[3] = f2tf32(v.w);
        }
#pragma unroll
        for (int it = 0; it < 4; it++) {          // B: 32x128
            int i  = tid + it * 256;
            int kr = i >> 5;
            int nq = (i & 31) * 4;
            float4 v = *reinterpret_cast<const float4*>(B + (size_t)(k0 + kr) * N + bn + nq);
            unsigned* d = &Bs[kr][nq];
            d[0] = f2tf32(v.x); d[1] = f2tf32(v.y);
            d[2] = f2tf32(v.z); d[3] = f2tf32(v.w);
        }
        __syncthreads();

#pragma unroll
        for (int kk = 0; kk < 32; kk += 8) {
            unsigned af[4][4], bf[4][2];
#pragma unroll
            for (int mt = 0; mt < 4; mt++) {
                int mb = wm + mt * 16;
                af[mt][0] = As[mb + r    ][kk + q];
                af[mt][1] = As[mb + r + 8][kk + q];
                af[mt][2] = As[mb + r    ][kk + q + 4];
                af[mt][3] = As[mb + r + 8][kk + q + 4];
            }
#pragma unroll
            for (int nt = 0; nt < 4; nt++) {
                int nb = wn + nt * 8 + r;
                bf[nt][0] = Bs[kk + q    ][nb];
                bf[nt][1] = Bs[kk + q + 4][nb];
            }
#pragma unroll
            for (int mt = 0; mt < 4; mt++)
#pragma unroll
                for (int nt = 0; nt < 4; nt++)
                    mma_tf32(acc[mt][nt], af[mt][0], af[mt][1], af[mt][2], af[mt][3],
                             bf[nt][0], bf[nt][1]);
        }
        __syncthreads();
    }

#pragma unroll
    for (int mt = 0; mt < 4; mt++) {
#pragma unroll
        for (int nt = 0; nt < 4; nt++) {
            int row = bm + wm + mt * 16 + r;
            int col = bn + wn + nt * 8 + 2 * q;
            float b0 = bias[col], b1 = bias[col + 1];
            float z00 = acc[mt][nt][0] + b0, z01 = acc[mt][nt][1] + b1;
            float z10 = acc[mt][nt][2] + b0, z11 = acc[mt][nt][3] + b1;
            if (do_gelu) {
                z00 = gelu_f(z00); z01 = gelu_f(z01);
                z10 = gelu_f(z10); z11 = gelu_f(z11);
            }
            float2 o0 = make_float2(z00, z01);
            float2 o1 = make_float2(z10, z11);
            *reinterpret_cast<float2*>(C + (size_t)row * N + col) = o0;
            *reinterpret_cast<float2*>(C + (size_t)(row + 8) * N + col) = o1;
        }
    }
}

// ---------------- persistent fused LSTM recurrence --------------------------
// 64 blocks (32 j-tiles x 2 batch-tiles), weight-stationary in smem, cell
// state in smem, h ping-pongs through g_hT (tf32-rounded), grid barrier/step.
#define WS_STRIDE 72
#define AS_STRIDE 36
#define WS_ELEMS  (LSTMD * WS_STRIDE)          /* 36864 u32 */
#define AS_ELEMS  (128 * AS_STRIDE)            /* 4608 u32 per buf */
#define CS_STRIDE 17
#define SMEM_LSTM ((WS_ELEMS + 2 * AS_ELEMS) * 4 + 128 * CS_STRIDE * 4)

__device__ __forceinline__ void grid_bar(unsigned target) {
    __syncthreads();
    if (threadIdx.x == 0) {
        __threadfence();
        atomicAdd(&g_bar, 1u);
        unsigned v;
        for (;;) {
            asm volatile("ld.acquire.gpu.u32 %0, [%1];" : "=r"(v) : "l"(&g_bar) : "memory");
            if (v >= target) break;
            __nanosleep(64);
        }
    }
    __syncthreads();
}

__global__ void __launch_bounds__(256, 1)
lstm_persistent(const unsigned* __restrict__ Wp,
                const float* __restrict__ gates,
                float* __restrict__ ys)
{
    extern __shared__ unsigned smem[];
    unsigned* Ws  = smem;                         // [512][72]
    unsigned* As0 = smem + WS_ELEMS;              // [2][128][36]
    float*    Cs  = (float*)(smem + WS_ELEMS + 2 * AS_ELEMS);  // [128][17]

    const int jt = blockIdx.x;          // 0..31
    const int bt = blockIdx.y;          // 0..1
    const int bn = jt * 64;
    const int bm = bt * 128;
    const int tid  = threadIdx.x;
    const int warp = tid >> 5;
    const int lane = tid & 31;
    const int wm = (warp & 3) * 32;     // 4 m-warps
    const int wn = (warp >> 2) * 32;    // 2 n-warps
    const int r  = lane >> 2;
    const int q  = lane & 3;
    const int p  = q & 1;

    // load W tile (512 x 64) once; zero cell state
    for (int i = tid; i < LSTMD * 16; i += 256) {   // uint4 count 512*64/4
        int k  = i >> 4;
        int nq = (i & 15) * 4;
        uint4 v = *reinterpret_cast<const uint4*>(Wp + (size_t)k * GATES_N + bn + nq);
        *reinterpret_cast<uint4*>(&Ws[k * WS_STRIDE + nq]) = v;
    }
    for (int i = tid; i < 128 * CS_STRIDE; i += 256) Cs[i] = 0.0f;
    __syncthreads();

    const unsigned nb = gridDim.x * gridDim.y;   // 64

    for (int t = 0; t < T_STEPS; t++) {
        const float* hin  = g_hT + ((t & 1) ? HT_ELEMS : 0);
        float*       hout = g_hT + ((t & 1) ? 0 : HT_ELEMS);
        const float* gx   = gates + (size_t)t * BATCH * GATES_N;

        // prefetch gx (DRAM) into registers
        float2 gxr[2][4][2];
#pragma unroll
        for (int mt = 0; mt < 2; mt++)
#pragma unroll
            for (int nt = 0; nt < 4; nt++) {
                int row = bm + wm + mt * 16 + r;
                int col = bn + wn + nt * 8 + 2 * q;
                gxr[mt][nt][0] = *reinterpret_cast<const float2*>(
                    gx + (size_t)row * GATES_N + col);
                gxr[mt][nt][1] = *reinterpret_cast<const float2*>(
                    gx + (size_t)(row + 8) * GATES_N + col);
            }

        float acc[2][4][4];
#pragma unroll
        for (int mt = 0; mt < 2; mt++)
#pragma unroll
            for (int nt = 0; nt < 4; nt++)
#pragma unroll
                for (int i = 0; i < 4; i++) acc[mt][nt][i] = 0.0f;

        // prefetch chunk 0
        {
            unsigned* A = As0;
#pragma unroll
            for (int it = 0; it < 4; it++) {
                int i  = tid + it * 256;
                int m  = i >> 3;
                int kq = (i & 7) * 4;
                cp16(&A[m * AS_STRIDE + kq], hin + (size_t)(bm + m) * LSTMD + kq);
            }
            cp_commit();
        }

        for (int c = 0; c < 16; c++) {
            if (c < 15) {
                unsigned* A = As0 + ((c + 1) & 1) * AS_ELEMS;
                int kb = (c + 1) * 32;
#pragma unroll
                for (int it = 0; it < 4; it++) {
                    int i  = tid + it * 256;
                    int m  = i >> 3;
                    int kq = (i & 7) * 4;
                    cp16(&A[m * AS_STRIDE + kq],
                         hin + (size_t)(bm + m) * LSTMD + kb + kq);
                }
                cp_commit();
                cp_wait<1>();
            } else {
                cp_wait<0>();
            }
            __syncthreads();

            const unsigned* A = As0 + (c & 1) * AS_ELEMS;
            const int kbase = c * 32;
#pragma unroll
            for (int kk = 0; kk < 32; kk += 8) {
                unsigned af[2][4], bf[4][2];
#pragma unroll
                for (int mt = 0; mt < 2; mt++) {
                    int mb = wm + mt * 16;
                    af[mt][0] = A[(mb + r    ) * AS_STRIDE + kk + q];
                    af[mt][1] = A[(mb + r + 8) * AS_STRIDE + kk + q];
                    af[mt][2] = A[(mb + r    ) * AS_STRIDE + kk + q + 4];
                    af[mt][3] = A[(mb + r + 8) * AS_STRIDE + kk + q + 4];
                }
#pragma unroll
                for (int nt = 0; nt < 4; nt++) {
                    int nc = wn + nt * 8 + r;
                    bf[nt][0] = Ws[(kbase + kk + q    ) * WS_STRIDE + nc];
                    bf[nt][1] = Ws[(kbase + kk + q + 4) * WS_STRIDE + nc];
                }
#pragma unroll
                for (int mt = 0; mt < 2; mt++)
#pragma unroll
                    for (int nt = 0; nt < 4; nt++)
                        mma_tf32(acc[mt][nt], af[mt][0], af[mt][1], af[mt][2], af[mt][3],
                                 bf[nt][0], bf[nt][1]);
            }
            __syncthreads();
        }

        // epilogue: gates + cell update; write ys (fp32) and hout (tf32-rounded)
        float* yst = ys + (size_t)t * BATCH * LSTMD;
#pragma unroll
        for (int mt = 0; mt < 2; mt++) {
#pragma unroll
            for (int nt = 0; nt < 4; nt++) {
                int lrow = wm + mt * 16 + r;
                int lcol = wn + nt * 8 + 2 * q;
                float z00 = acc[mt][nt][0] + gxr[mt][nt][0].x;
                float z01 = acc[mt][nt][1] + gxr[mt][nt][0].y;
                float z10 = acc[mt][nt][2] + gxr[mt][nt][1].x;
                float z11 = acc[mt][nt][3] + gxr[mt][nt][1].y;

                // p==0: (z00,z01)=(i,f); p==1: (g,o)
                float u0a = (p == 0) ? sigm(z00) : tanhf(z00);
                float u1a = sigm(z01);
                float u0b = (p == 0) ? sigm(z10) : tanhf(z10);
                float u1b = sigm(z11);

                float v0a = __shfl_xor_sync(0xffffffffu, u0a, 1);
                float v1a = __shfl_xor_sync(0xffffffffu, u1a, 1);
                float v0b = __shfl_xor_sync(0xffffffffu, u0b, 1);
                float v1b = __shfl_xor_sync(0xffffffffu, u1b, 1);

                if (p == 0) {
                    int jl = lcol >> 2;                  // 0..15
                    int jg = jt * 16 + jl;
                    {
                        float co = Cs[lrow * CS_STRIDE + jl];
                        float cn = u1a * co + u0a * v0a;
                        Cs[lrow * CS_STRIDE + jl] = cn;
                        float h = v1a * tanhf(cn);
                        size_t gi = (size_t)(bm + lrow) * LSTMD + jg;
                        yst[gi]  = h;
                        hout[gi] = __uint_as_float(f2tf32(h));
                    }
                    {
                        int lr2 = lrow + 8;
                        float co = Cs[lr2 * CS_STRIDE + jl];
                        float cn = u1b * co + u0b * v0b;
                        Cs[lr2 * CS_STRIDE + jl] = cn;
                        float h = v1b * tanhf(cn);
                        size_t gi = (size_t)(bm + lr2) * LSTMD + jg;
                        yst[gi]  = h;
                        hout[gi] = __uint_as_float(f2tf32(h));
                    }
                }
            }
        }

        grid_bar((unsigned)(t + 1) * nb);
    }
}

// ---------------- heads: mu / sigma / value, one pass over ys ---------------
__global__ void heads_kernel(const float* __restrict__ Wmu,
                             const float* __restrict__ bmu,
                             const float* __restrict__ logstd,
                             const float* __restrict__ Wv,
                             const float* __restrict__ bv,
                             float* __restrict__ out)
{
    const int lane = threadIdx.x;
    const size_t row = (size_t)blockIdx.x * blockDim.y + threadIdx.y;
    const float* yrow = g_ys + row * LSTMD;

    float acc = 0.0f;
#pragma unroll 8
    for (int k = 0; k < LSTMD; k++)
        acc = fmaf(yrow[k], Wmu[k * ACTD + lane], acc);

    float* mu    = out;
    float* sigma = out + (size_t)ROWS * ACTD;
    float* value = out + (size_t)2 * ROWS * ACTD;

    mu[row * ACTD + lane]    = acc + bmu[lane];
    sigma[row * ACTD + lane] = expf(logstd[lane]);

    float v = 0.0f;
    for (int k = lane; k < LSTMD; k += 32)
        v = fmaf(yrow[k], Wv[k], v);
#pragma unroll
    for (int o = 16; o; o >>= 1) v += __shfl_xor_sync(0xffffffffu, v, o);
    if (lane == 0) value[row] = v + bv[0];
}

// ---------------- launch ----------------------------------------------------
extern "C" void kernel_launch(void* const* d_in, const int* in_sizes, int n_in,
                              void* d_out, int out_size)
{
    (void)in_sizes; (void)n_in; (void)out_size;
    const float* x      = (const float*)d_in[0];
    const float* W_enc  = (const float*)d_in[1];
    const float* b_enc  = (const float*)d_in[2];
    const float* W_i    = (const float*)d_in[3];
    const float* W_h    = (const float*)d_in[4];
    const float* b_lstm = (const float*)d_in[5];
    const float* W_mu   = (const float*)d_in[6];
    const float* b_mu   = (const float*)d_in[7];
    const float* logstd = (const float*)d_in[8];
    const float* W_v    = (const float*)d_in[9];
    const float* b_v    = (const float*)d_in[10];
    float* out = (float*)d_out;

    float *feats, *gates, *ys, *hT, *WiP, *bP;
    unsigned* WhP;
    cudaGetSymbolAddress((void**)&feats, g_feats);
    cudaGetSymbolAddress((void**)&gates, g_gates);
    cudaGetSymbolAddress((void**)&ys,    g_ys);
    cudaGetSymbolAddress((void**)&hT,    g_hT);
    cudaGetSymbolAddress((void**)&WiP,   g_WiP);
    cudaGetSymbolAddress((void**)&WhP,   g_WhP);
    cudaGetSymbolAddress((void**)&bP,    g_bP);

    static int smem_set = 0;
    if (!smem_set) {
        cudaFuncSetAttribute(lstm_persistent,
                             cudaFuncAttributeMaxDynamicSharedMemorySize, SMEM_LSTM);
        smem_set = 1;
    }

    // zero h ping-pong buffer 0 + barrier counter
    zero_kernel<<<(HT_ELEMS + 255) / 256, 256>>>(hT, HT_ELEMS);
    zero_bar<<<1, 1>>>();

    // permute weights into 4j+g interleaved layout (W_h also -> tf32)
    permute_wi<<<(HIDD * GATES_N) / 256, 256>>>(W_i, WiP);
    permute_wh<<<(LSTMD * GATES_N) / 256, 256>>>(W_h, WhP);
    permute_b<<<(GATES_N + 255) / 256, 256>>>(b_lstm, bP);

    // encoder: feats = gelu(x @ W_enc + b_enc)   [131072 x 512, K=256]
    {
        dim3 grid(HIDD / 128, ROWS / 128);
        gemm_mma<<<grid, 256>>>(x, W_enc, b_enc, feats, ROWS, HIDD, OBSD, 1);
    }
    // gates = feats @ WiP + bP   (permuted cols)  [131072 x 2048, K=512]
    {
        dim3 grid(GATES_N / 128, ROWS / 128);
        gemm_mma<<<grid, 256>>>(feats, WiP, bP, gates, ROWS, GATES_N, HIDD, 0);
    }
    // recurrence: single persistent kernel, 64 co-resident blocks
    {
        dim3 grid(GATES_N / 64 / 4, BATCH / 128);   // wait: 32 j-tiles x 2 b-tiles
        grid.x = 32; grid.y = 2;
        lstm_persistent<<<grid, 256, SMEM_LSTM>>>(WhP, gates, ys);
    }
    // heads
    {
        dim3 blk(32, 8);
        heads_kernel<<<ROWS / 8, blk>>>(W_mu, b_mu, logstd, W_v, b_v, out);
    }
}

// round 4
// speedup vs baseline: 3.0068x; 1.4677x over previous
#include <cuda_runtime.h>
#include <math.h>

#define T_STEPS 512
#define BATCH   256
#define OBSD    256
#define HIDD    512
#define LSTMD   512
#define ACTD    32
#define ROWS    (T_STEPS * BATCH)   /* 131072 */
#define GATES_N (4 * LSTMD)         /* 2048 */
#define HT_ELEMS (BATCH * LSTMD)    /* 131072 */

// ---------------- scratch (static device globals; no runtime allocation) ----
__device__ float    g_xr   [(size_t)ROWS * OBSD];          // tf32-rounded x
__device__ float    g_WencR[(size_t)OBSD * HIDD];          // tf32-rounded W_enc
__device__ float    g_feats[(size_t)ROWS * HIDD];          // tf32-rounded feats
__device__ float    g_gates[(size_t)ROWS * GATES_N];       // 1 GB (permuted 4j+g)
__device__ float    g_ys   [(size_t)ROWS * LSTMD];         // 256 MB
__device__ float    g_hT   [2 * HT_ELEMS];                 // ping-pong h (tf32)
__device__ float    g_WiP  [(size_t)HIDD * GATES_N];       // permuted+rounded W_i
__device__ unsigned g_WhP  [(size_t)LSTMD * GATES_N];      // permuted W_h (tf32)
__device__ float    g_bP   [GATES_N];                      // permuted b_lstm
__device__ unsigned g_bar;                                 // grid barrier counter

__device__ __forceinline__ float gelu_f(float x) {
    float x3 = x * x * x;
    float t  = tanhf(0.7978845608028654f * (x + 0.044715f * x3));
    return 0.5f * x * (1.0f + t);
}
__device__ __forceinline__ float sigm(float x) { return 1.0f / (1.0f + expf(-x)); }

__device__ __forceinline__ unsigned f2tf32(float x) {
    unsigned u;
    asm("cvt.rna.tf32.f32 %0, %1;" : "=r"(u) : "f"(x));
    return u;
}

__device__ __forceinline__ void mma_tf32(float c[4],
                                         unsigned a0, unsigned a1, unsigned a2, unsigned a3,
                                         unsigned b0, unsigned b1) {
    asm volatile(
        "mma.sync.aligned.m16n8k8.row.col.f32.tf32.tf32.f32 "
        "{%0,%1,%2,%3}, {%4,%5,%6,%7}, {%8,%9}, {%0,%1,%2,%3};\n"
        : "+f"(c[0]), "+f"(c[1]), "+f"(c[2]), "+f"(c[3])
        : "r"(a0), "r"(a1), "r"(a2), "r"(a3), "r"(b0), "r"(b1));
}

__device__ __forceinline__ void cp16(void* smem_dst, const void* gsrc) {
    unsigned d = (unsigned)__cvta_generic_to_shared(smem_dst);
    asm volatile("cp.async.ca.shared.global [%0], [%1], 16;\n" :: "r"(d), "l"(gsrc));
}
__device__ __forceinline__ void cp_commit() {
    asm volatile("cp.async.commit_group;\n");
}
template <int N>
__device__ __forceinline__ void cp_wait() {
    asm volatile("cp.async.wait_group %0;\n" :: "n"(N));
}

// ---------------- small utility kernels -------------------------------------
__global__ void zero_kernel(float* p, int n) {
    int i = blockIdx.x * blockDim.x + threadIdx.x;
    if (i < n) p[i] = 0.0f;
}
__global__ void zero_bar() { g_bar = 0u; }

__global__ void round4_kernel(const float4* __restrict__ in,
                              float4* __restrict__ out, int n4) {
    int i = blockIdx.x * blockDim.x + threadIdx.x;
    if (i < n4) {
        float4 v = in[i];
        v.x = __uint_as_float(f2tf32(v.x));
        v.y = __uint_as_float(f2tf32(v.y));
        v.z = __uint_as_float(f2tf32(v.z));
        v.w = __uint_as_float(f2tf32(v.w));
        out[i] = v;
    }
}

// Wp[k][4j+g] = round(W[k][g*512+j])
__global__ void permute_wi(const float* __restrict__ W, float* __restrict__ Wp) {
    int idx = blockIdx.x * 256 + threadIdx.x;       // < 512*2048
    int k = idx >> 11, c = idx & 2047;
    Wp[idx] = __uint_as_float(f2tf32(W[(size_t)k * GATES_N + (c & 3) * LSTMD + (c >> 2)]));
}
__global__ void permute_wh(const float* __restrict__ W, unsigned* __restrict__ Wp) {
    int idx = blockIdx.x * 256 + threadIdx.x;
    int k = idx >> 11, c = idx & 2047;
    Wp[idx] = f2tf32(W[(size_t)k * GATES_N + (c & 3) * LSTMD + (c >> 2)]);
}
__global__ void permute_b(const float* __restrict__ b, float* __restrict__ bp) {
    int idx = blockIdx.x * 256 + threadIdx.x;
    if (idx < GATES_N) bp[idx] = b[(idx & 3) * LSTMD + (idx >> 2)];
}

// ---------------- big GEMM: C = act(A @ B + bias), cp.async double-buffered -
// BM=128, BN=128, BK=32, 256 threads (8 warps: 2m x 4n of 64x32 warp tiles).
// A, B must already be tf32-rounded fp32.
#define GA_STRIDE 36
#define GB_STRIDE 136
#define GA_ELEMS  (128 * GA_STRIDE)   /* 4608 */
#define GB_ELEMS  (32 * GB_STRIDE)    /* 4352 */
#define SMEM_GEMM ((2 * GA_ELEMS + 2 * GB_ELEMS) * 4)

__global__ void __launch_bounds__(256)
gemm_mma(const float* __restrict__ A,
         const float* __restrict__ B,
         const float* __restrict__ bias,
         float* __restrict__ C,
         int M, int N, int K, int do_gelu, int do_round)
{
    extern __shared__ unsigned gsm[];
    unsigned* As = gsm;                   // [2][128][36]
    unsigned* Bs = gsm + 2 * GA_ELEMS;    // [2][32][136]

    const int bm = blockIdx.y * 128;
    const int bn = blockIdx.x * 128;
    const int tid  = threadIdx.x;
    const int warp = tid >> 5;
    const int lane = tid & 31;
    const int wm = (warp & 1) * 64;
    const int wn = (warp >> 1) * 32;
    const int r  = lane >> 2;
    const int q  = lane & 3;

    float acc[4][4][4];
#pragma unroll
    for (int mt = 0; mt < 4; mt++)
#pragma unroll
        for (int nt = 0; nt < 4; nt++)
#pragma unroll
            for (int i = 0; i < 4; i++) acc[mt][nt][i] = 0.0f;

    const float* Ab = A + (size_t)bm * K;
    const int nK = K >> 5;

    // stage loader
    auto load_stage = [&](int kt, int buf) {
        unsigned* Ad = As + buf * GA_ELEMS;
        unsigned* Bd = Bs + buf * GB_ELEMS;
        int k0 = kt * 32;
#pragma unroll
        for (int it = 0; it < 4; it++) {          // A 128x32
            int i  = tid + it * 256;
            int m  = i >> 3;
            int kq = (i & 7) * 4;
            cp16(&Ad[m * GA_STRIDE + kq], Ab + (size_t)m * K + k0 + kq);
        }
#pragma unroll
        for (int it = 0; it < 4; it++) {          // B 32x128
            int i  = tid + it * 256;
            int kr = i >> 5;
            int nq = (i & 31) * 4;
            cp16(&Bd[kr * GB_STRIDE + nq], B + (size_t)(k0 + kr) * N + bn + nq);
        }
        cp_commit();
    };

    load_stage(0, 0);

    for (int kt = 0; kt < nK; kt++) {
        if (kt + 1 < nK) { load_stage(kt + 1, (kt + 1) & 1); cp_wait<1>(); }
        else             { cp_wait<0>(); }
        __syncthreads();

        const unsigned* Ac = As + (kt & 1) * GA_ELEMS;
        const unsigned* Bc = Bs + (kt & 1) * GB_ELEMS;
#pragma unroll
        for (int kk = 0; kk < 32; kk += 8) {
            unsigned af[4][4], bf[4][2];
#pragma unroll
            for (int mt = 0; mt < 4; mt++) {
                int mb = wm + mt * 16;
                af[mt][0] = Ac[(mb + r    ) * GA_STRIDE + kk + q];
                af[mt][1] = Ac[(mb + r + 8) * GA_STRIDE + kk + q];
                af[mt][2] = Ac[(mb + r    ) * GA_STRIDE + kk + q + 4];
                af[mt][3] = Ac[(mb + r + 8) * GA_STRIDE + kk + q + 4];
            }
#pragma unroll
            for (int nt = 0; nt < 4; nt++) {
                int nb = wn + nt * 8 + r;
                bf[nt][0] = Bc[(kk + q    ) * GB_STRIDE + nb];
                bf[nt][1] = Bc[(kk + q + 4) * GB_STRIDE + nb];
            }
#pragma unroll
            for (int mt = 0; mt < 4; mt++)
#pragma unroll
                for (int nt = 0; nt < 4; nt++)
                    mma_tf32(acc[mt][nt], af[mt][0], af[mt][1], af[mt][2], af[mt][3],
                             bf[nt][0], bf[nt][1]);
        }
        __syncthreads();
    }

#pragma unroll
    for (int mt = 0; mt < 4; mt++) {
#pragma unroll
        for (int nt = 0; nt < 4; nt++) {
            int row = bm + wm + mt * 16 + r;
            int col = bn + wn + nt * 8 + 2 * q;
            float b0 = bias[col], b1 = bias[col + 1];
            float z00 = acc[mt][nt][0] + b0, z01 = acc[mt][nt][1] + b1;
            float z10 = acc[mt][nt][2] + b0, z11 = acc[mt][nt][3] + b1;
            if (do_gelu) {
                z00 = gelu_f(z00); z01 = gelu_f(z01);
                z10 = gelu_f(z10); z11 = gelu_f(z11);
            }
            if (do_round) {
                z00 = __uint_as_float(f2tf32(z00));
                z01 = __uint_as_float(f2tf32(z01));
                z10 = __uint_as_float(f2tf32(z10));
                z11 = __uint_as_float(f2tf32(z11));
            }
            float2 o0 = make_float2(z00, z01);
            float2 o1 = make_float2(z10, z11);
            *reinterpret_cast<float2*>(C + (size_t)row * N + col) = o0;
            *reinterpret_cast<float2*>(C + (size_t)(row + 8) * N + col) = o1;
        }
    }
}

// ---------------- persistent fused LSTM recurrence --------------------------
// 128 blocks (32 j-tiles x 4 batch-tiles of 64 rows), weight-stationary,
// cell state in smem, h ping-pongs via g_hT, grid barrier per step.
#define WS_STRIDE 72
#define AS_STRIDE 68
#define WS_ELEMS  (LSTMD * WS_STRIDE)          /* 36864 u32 = 144KB */
#define AS_ELEMS  (64 * AS_STRIDE)             /* 4352 u32 per buf  */
#define CS_STRIDE 17
#define SMEM_LSTM ((WS_ELEMS + 2 * AS_ELEMS) * 4 + 64 * CS_STRIDE * 4)
#define NBLK      128

__device__ __forceinline__ void grid_bar(unsigned target) {
    __syncthreads();
    if (threadIdx.x == 0) {
        __threadfence();
        atomicAdd(&g_bar, 1u);
        unsigned v;
        for (;;) {
            asm volatile("ld.acquire.gpu.u32 %0, [%1];" : "=r"(v) : "l"(&g_bar) : "memory");
            if (v >= target) break;
            __nanosleep(32);
        }
    }
    __syncthreads();
}

__global__ void __launch_bounds__(256, 1)
lstm_persistent(const unsigned* __restrict__ Wp,
                const float* __restrict__ gates,
                float* __restrict__ ys)
{
    extern __shared__ unsigned smem[];
    unsigned* Ws  = smem;                          // [512][72]
    unsigned* As0 = smem + WS_ELEMS;               // [2][64][68]
    float*    Cs  = (float*)(smem + WS_ELEMS + 2 * AS_ELEMS);  // [64][17]

    const int jt = blockIdx.x;          // 0..31
    const int bt = blockIdx.y;          // 0..3
    const int bn = jt * 64;             // gate-col base
    const int bm = bt * 64;             // batch-row base
    const int tid  = threadIdx.x;
    const int warp = tid >> 5;
    const int lane = tid & 31;
    const int wm = (warp & 1) * 32;     // 2 m-warps of 32 rows
    const int wn = (warp >> 1) * 16;    // 4 n-warps of 16 cols
    const int r  = lane >> 2;
    const int q  = lane & 3;
    const int p  = q & 1;

    // load W tile (512 x 64) once; zero cell state
    for (int i = tid; i < LSTMD * 16; i += 256) {
        int k  = i >> 4;
        int nq = (i & 15) * 4;
        uint4 v = *reinterpret_cast<const uint4*>(Wp + (size_t)k * GATES_N + bn + nq);
        *reinterpret_cast<uint4*>(&Ws[k * WS_STRIDE + nq]) = v;
    }
    for (int i = tid; i < 64 * CS_STRIDE; i += 256) Cs[i] = 0.0f;
    __syncthreads();

    for (int t = 0; t < T_STEPS; t++) {
        const float* hin  = g_hT + ((t & 1) ? HT_ELEMS : 0);
        float*       hout = g_hT + ((t & 1) ? 0 : HT_ELEMS);
        const float* gx   = gates + (size_t)t * BATCH * GATES_N;

        // prefetch gx into registers
        float2 gxr[2][2][2];
#pragma unroll
        for (int mt = 0; mt < 2; mt++)
#pragma unroll
            for (int nt = 0; nt < 2; nt++) {
                int row = bm + wm + mt * 16 + r;
                int col = bn + wn + nt * 8 + 2 * q;
                gxr[mt][nt][0] = *reinterpret_cast<const float2*>(
                    gx + (size_t)row * GATES_N + col);
                gxr[mt][nt][1] = *reinterpret_cast<const float2*>(
                    gx + (size_t)(row + 8) * GATES_N + col);
            }

        float acc[2][2][4];
#pragma unroll
        for (int mt = 0; mt < 2; mt++)
#pragma unroll
            for (int nt = 0; nt < 2; nt++)
#pragma unroll
                for (int i = 0; i < 4; i++) acc[mt][nt][i] = 0.0f;

        // prefetch chunk 0 (64 rows x 64 k)
        {
            unsigned* A = As0;
#pragma unroll
            for (int it = 0; it < 4; it++) {
                int i  = tid + it * 256;
                int m  = i >> 4;
                int kq = (i & 15) * 4;
                cp16(&A[m * AS_STRIDE + kq], hin + (size_t)(bm + m) * LSTMD + kq);
            }
            cp_commit();
        }

        for (int c = 0; c < 8; c++) {
            if (c < 7) {
                unsigned* A = As0 + ((c + 1) & 1) * AS_ELEMS;
                int kb = (c + 1) * 64;
#pragma unroll
                for (int it = 0; it < 4; it++) {
                    int i  = tid + it * 256;
                    int m  = i >> 4;
                    int kq = (i & 15) * 4;
                    cp16(&A[m * AS_STRIDE + kq],
                         hin + (size_t)(bm + m) * LSTMD + kb + kq);
                }
                cp_commit();
                cp_wait<1>();
            } else {
                cp_wait<0>();
            }
            __syncthreads();

            const unsigned* A = As0 + (c & 1) * AS_ELEMS;
            const int kbase = c * 64;
#pragma unroll
            for (int kk = 0; kk < 64; kk += 8) {
                unsigned af[2][4], bf[2][2];
#pragma unroll
                for (int mt = 0; mt < 2; mt++) {
                    int mb = wm + mt * 16;
                    af[mt][0] = A[(mb + r    ) * AS_STRIDE + kk + q];
                    af[mt][1] = A[(mb + r + 8) * AS_STRIDE + kk + q];
                    af[mt][2] = A[(mb + r    ) * AS_STRIDE + kk + q + 4];
                    af[mt][3] = A[(mb + r + 8) * AS_STRIDE + kk + q + 4];
                }
#pragma unroll
                for (int nt = 0; nt < 2; nt++) {
                    int nc = wn + nt * 8 + r;
                    bf[nt][0] = Ws[(kbase + kk + q    ) * WS_STRIDE + nc];
                    bf[nt][1] = Ws[(kbase + kk + q + 4) * WS_STRIDE + nc];
                }
#pragma unroll
                for (int mt = 0; mt < 2; mt++)
#pragma unroll
                    for (int nt = 0; nt < 2; nt++)
                        mma_tf32(acc[mt][nt], af[mt][0], af[mt][1], af[mt][2], af[mt][3],
                                 bf[nt][0], bf[nt][1]);
            }
            __syncthreads();
        }

        // epilogue: gates + cell update; write ys (fp32) + hout (tf32-rounded)
        float* yst = ys + (size_t)t * BATCH * LSTMD;
#pragma unroll
        for (int mt = 0; mt < 2; mt++) {
#pragma unroll
            for (int nt = 0; nt < 2; nt++) {
                int lrow = wm + mt * 16 + r;
                int lcol = wn + nt * 8 + 2 * q;
                float z00 = acc[mt][nt][0] + gxr[mt][nt][0].x;
                float z01 = acc[mt][nt][1] + gxr[mt][nt][0].y;
                float z10 = acc[mt][nt][2] + gxr[mt][nt][1].x;
                float z11 = acc[mt][nt][3] + gxr[mt][nt][1].y;

                float u0a = (p == 0) ? sigm(z00) : tanhf(z00);
                float u1a = sigm(z01);
                float u0b = (p == 0) ? sigm(z10) : tanhf(z10);
                float u1b = sigm(z11);

                float v0a = __shfl_xor_sync(0xffffffffu, u0a, 1);
                float v1a = __shfl_xor_sync(0xffffffffu, u1a, 1);
                float v0b = __shfl_xor_sync(0xffffffffu, u0b, 1);
                float v1b = __shfl_xor_sync(0xffffffffu, u1b, 1);

                if (p == 0) {
                    int jl = lcol >> 2;                  // 0..15
                    int jg = jt * 16 + jl;
                    {
                        float co = Cs[lrow * CS_STRIDE + jl];
                        float cn = u1a * co + u0a * v0a;
                        Cs[lrow * CS_STRIDE + jl] = cn;
                        float h = v1a * tanhf(cn);
                        size_t gi = (size_t)(bm + lrow) * LSTMD + jg;
                        yst[gi]  = h;
                        hout[gi] = __uint_as_float(f2tf32(h));
                    }
                    {
                        int lr2 = lrow + 8;
                        float co = Cs[lr2 * CS_STRIDE + jl];
                        float cn = u1b * co + u0b * v0b;
                        Cs[lr2 * CS_STRIDE + jl] = cn;
                        float h = v1b * tanhf(cn);
                        size_t gi = (size_t)(bm + lr2) * LSTMD + jg;
                        yst[gi]  = h;
                        hout[gi] = __uint_as_float(f2tf32(h));
                    }
                }
            }
        }

        grid_bar((unsigned)(t + 1) * NBLK);
    }
}

// ---------------- heads: mu / sigma / value, one pass over ys ---------------
__global__ void heads_kernel(const float* __restrict__ Wmu,
                             const float* __restrict__ bmu,
                             const float* __restrict__ logstd,
                             const float* __restrict__ Wv,
                             const float* __restrict__ bv,
                             float* __restrict__ out)
{
    const int lane = threadIdx.x;
    const size_t row = (size_t)blockIdx.x * blockDim.y + threadIdx.y;
    const float* yrow = g_ys + row * LSTMD;

    float acc = 0.0f;
#pragma unroll 8
    for (int k = 0; k < LSTMD; k++)
        acc = fmaf(yrow[k], Wmu[k * ACTD + lane], acc);

    float* mu    = out;
    float* sigma = out + (size_t)ROWS * ACTD;
    float* value = out + (size_t)2 * ROWS * ACTD;

    mu[row * ACTD + lane]    = acc + bmu[lane];
    sigma[row * ACTD + lane] = expf(logstd[lane]);

    float v = 0.0f;
    for (int k = lane; k < LSTMD; k += 32)
        v = fmaf(yrow[k], Wv[k], v);
#pragma unroll
    for (int o = 16; o; o >>= 1) v += __shfl_xor_sync(0xffffffffu, v, o);
    if (lane == 0) value[row] = v + bv[0];
}

// ---------------- launch ----------------------------------------------------
extern "C" void kernel_launch(void* const* d_in, const int* in_sizes, int n_in,
                              void* d_out, int out_size)
{
    (void)in_sizes; (void)n_in; (void)out_size;
    const float* x      = (const float*)d_in[0];
    const float* W_enc  = (const float*)d_in[1];
    const float* b_enc  = (const float*)d_in[2];
    const float* W_i    = (const float*)d_in[3];
    const float* W_h    = (const float*)d_in[4];
    const float* b_lstm = (const float*)d_in[5];
    const float* W_mu   = (const float*)d_in[6];
    const float* b_mu   = (const float*)d_in[7];
    const float* logstd = (const float*)d_in[8];
    const float* W_v    = (const float*)d_in[9];
    const float* b_v    = (const float*)d_in[10];
    float* out = (float*)d_out;

    float *xr, *WencR, *feats, *gates, *ys, *hT, *WiP, *bP;
    unsigned* WhP;
    cudaGetSymbolAddress((void**)&xr,    g_xr);
    cudaGetSymbolAddress((void**)&WencR, g_WencR);
    cudaGetSymbolAddress((void**)&feats, g_feats);
    cudaGetSymbolAddress((void**)&gates, g_gates);
    cudaGetSymbolAddress((void**)&ys,    g_ys);
    cudaGetSymbolAddress((void**)&hT,    g_hT);
    cudaGetSymbolAddress((void**)&WiP,   g_WiP);
    cudaGetSymbolAddress((void**)&WhP,   g_WhP);
    cudaGetSymbolAddress((void**)&bP,    g_bP);

    static int attr_set = 0;
    if (!attr_set) {
        cudaFuncSetAttribute(lstm_persistent,
                             cudaFuncAttributeMaxDynamicSharedMemorySize, SMEM_LSTM);
        cudaFuncSetAttribute(gemm_mma,
                             cudaFuncAttributeMaxDynamicSharedMemorySize, SMEM_GEMM);
        attr_set = 1;
    }

    // zero h ping-pong buffer 0 + barrier counter
    zero_kernel<<<(HT_ELEMS + 255) / 256, 256>>>(hT, HT_ELEMS);
    zero_bar<<<1, 1>>>();

    // pre-round x, W_enc to tf32; permute W_i (rounded) / W_h (tf32 bits) / b
    round4_kernel<<<(ROWS * OBSD / 4 + 255) / 256, 256>>>(
        (const float4*)x, (float4*)xr, ROWS * OBSD / 4);
    round4_kernel<<<(OBSD * HIDD / 4 + 255) / 256, 256>>>(
        (const float4*)W_enc, (float4*)WencR, OBSD * HIDD / 4);
    permute_wi<<<(HIDD * GATES_N) / 256, 256>>>(W_i, WiP);
    permute_wh<<<(LSTMD * GATES_N) / 256, 256>>>(W_h, WhP);
    permute_b<<<(GATES_N + 255) / 256, 256>>>(b_lstm, bP);

    // encoder: feats = round(gelu(xr @ WencR + b_enc))  [131072 x 512, K=256]
    {
        dim3 grid(HIDD / 128, ROWS / 128);
        gemm_mma<<<grid, 256, SMEM_GEMM>>>(xr, WencR, b_enc, feats,
                                           ROWS, HIDD, OBSD, 1, 1);
    }
    // gates = feats @ WiP + bP   [131072 x 2048, K=512]
    {
        dim3 grid(GATES_N / 128, ROWS / 128);
        gemm_mma<<<grid, 256, SMEM_GEMM>>>(feats, WiP, bP, gates,
                                           ROWS, GATES_N, HIDD, 0, 0);
    }
    // recurrence: single persistent kernel, 128 co-resident blocks
    {
        dim3 grid(32, 4);
        lstm_persistent<<<grid, 256, SMEM_LSTM>>>(WhP, gates, ys);
    }
    // heads
    {
        dim3 blk(32, 8);
        heads_kernel<<<ROWS / 8, blk>>>(W_mu, b_mu, logstd, W_v, b_v, out);
    }
}